// round 15
// baseline (speedup 1.0000x reference)
#include <cuda_runtime.h>
#include <cstdint>

#define BB 8192
#define SSAMP 8
#define HOR 4
#define NT 64   // 4 steps * 16 G2 K=16 tiles; G1+G3 on the FP32 pipe
#define TILE_M 64
#define KT 32

#if defined(__CUDA_ARCH__) && (defined(__CUDA_ARCH_FEAT_SM103_ALL) || defined(__CUDA_ARCH_FEAT_SM100_ALL) || defined(__CUDA_ARCH_SPECIFIC__))
#define HAS_TC 1
#else
#define HAS_TC 0
#endif

// idesc: F32 accum (1<<4) | atype TF32 (2<<7) | btype TF32 (2<<10) | (N/8)<<17 | (M/16)<<24
#define IDESC_N256 ((1u<<4)|(2u<<7)|(2u<<10)|(32u<<17)|(8u<<24))

// tc smem byte offsets (112 KB/CTA -> 2 CTAs/SM)
#define SO_TM   0
#define SO_MBF  16        // full mbars [2]
#define SO_MBD  32        // done mbars [2]
#define SO_B1   64        // 256 f
#define SO_B2   1088      // 256 f
#define SO_W3   2112      // 2304 f (w3 row-major [256][9])
#define SO_W1   11328     // 4096 f (w1 row-major [16][256])
#define SO_SIM  27712     // 128*9 f (sim handoff wg0 -> all)
#define SO_A    32768     // A slot (16KB): hi @ +0, lo @ +8192 ; s_pt overlays here in epilogue
#define SO_B    49152     // B slot s (32KB): hi @ +0, lo @ +16384  (2 slots)
#define SMEMSZ  114688

// fb smem
#define FB_FLOATS 49104
#define FB_BYTES  (FB_FLOATS * 4)

typedef unsigned long long u64;

__device__ float g_cand[SSAMP*BB*7];
__device__ float g_cost[SSAMP*BB];
// prepped w2: SW64-swizzled K-major K=16 tiles (64B rows), [hi][lo]
__device__ __align__(128) uint32_t g_w2[16][2*4096];

// ------------------------- shared helpers ----------------------------------
__device__ __forceinline__ void split_tf32(float v, uint32_t& hi, uint32_t& lo){
    asm("cvt.rna.tf32.f32 %0, %1;":"=r"(hi):"f"(v));
    float r = v - __uint_as_float(hi);
    asm("cvt.rna.tf32.f32 %0, %1;":"=r"(lo):"f"(r));
}
__device__ __forceinline__ uint32_t swz64(uint32_t b){ return b ^ ((b>>3)&0x30u); }

struct F4 { float v[4]; };
__device__ __forceinline__ F4 ld4s(const float* p){
    float4 t = *reinterpret_cast<const float4*>(p);
    F4 r; r.v[0]=t.x; r.v[1]=t.y; r.v[2]=t.z; r.v[3]=t.w; return r;
}
__device__ __forceinline__ u64 dup2f(float x){
    u64 r; asm("mov.b64 %0, {%1, %2};" : "=l"(r) : "f"(x), "f"(x)); return r;
}
__device__ __forceinline__ void fma2(u64& d, u64 a, u64 b){
    asm("fma.rn.f32x2 %0, %1, %2, %3;" : "=l"(d) : "l"(a), "l"(b), "l"(d));
}
__device__ __forceinline__ float2 unpk(u64 x){
    float2 f; asm("mov.b64 {%0, %1}, %2;" : "=f"(f.x), "=f"(f.y) : "l"(x)); return f;
}
__device__ __forceinline__ u64 relu2(u64 x){
    float2 f = unpk(x);
    f.x = fmaxf(f.x, 0.0f); f.y = fmaxf(f.y, 0.0f);
    u64 r; asm("mov.b64 %0, {%1, %2};" : "=l"(r) : "f"(f.x), "f"(f.y)); return r;
}
__device__ __forceinline__ void cp16(float* smem_dst, const float* gsrc){
    uint32_t d = (uint32_t)__cvta_generic_to_shared(smem_dst);
    asm volatile("cp.async.cg.shared.global [%0], [%1], 16;\n" :: "r"(d), "l"(gsrc));
}
__device__ __forceinline__ void cp_commit(){ asm volatile("cp.async.commit_group;\n" ::); }
__device__ __forceinline__ void cp_wait1(){ asm volatile("cp.async.wait_group 1;\n" ::); }
__device__ __forceinline__ void cp_wait0(){ asm volatile("cp.async.wait_group 0;\n" ::); }

// ------------------------- tc-only helpers ---------------------------------
#if HAS_TC
__device__ __forceinline__ uint32_t smem_u32(const void* p){
    uint32_t a; asm("{ .reg .u64 t; cvta.to.shared.u64 t, %1; cvt.u32.u64 %0, t; }":"=r"(a):"l"(p)); return a;
}
__device__ __forceinline__ uint32_t elect_one(){
    uint32_t p; asm volatile("{ .reg .pred q; elect.sync _|q, 0xFFFFFFFF; selp.b32 %0,1,0,q; }":"=r"(p)); return p;
}
// SW64 K-major descriptor: layout=4, v1, SBO=32, LBO=1  (validated in R14)
__device__ __forceinline__ uint64_t sdesc64(uint32_t a){
    return ((uint64_t)4<<61)|((uint64_t)1<<46)|((uint64_t)32<<32)|((uint64_t)1<<16)|((uint64_t)(a>>4)&0x3FFF);
}
__device__ __forceinline__ void wait_par(uint32_t mb, uint32_t par){
    asm volatile("{\n\t.reg .pred P;\nWL%=:\n\tmbarrier.try_wait.parity.acquire.cta.shared::cta.b64 P,[%0],%1,0x989680;\n\t@P bra.uni WD%=;\n\tbra.uni WL%=;\nWD%=:\n\t}"::"r"(mb),"r"(par):"memory");
}
#define WAIT_DONE(i) wait_par(sb+SO_MBD+8u*((uint32_t)(i)&1u), ((uint32_t)(i)>>1)&1u)
#define WAIT_FULL(i) wait_par(sb+SO_MBF+8u*((uint32_t)(i)&1u), ((uint32_t)(i)>>1)&1u)
#define FENCE_AFTER()  asm volatile("tcgen05.fence::after_thread_sync;":::"memory")
#define FENCE_ASYNC()  asm volatile("fence.proxy.async.shared::cta;":::"memory")
#define TM_WAIT_LD()   asm volatile("tcgen05.wait::ld.sync.aligned;":::"memory")

__device__ __forceinline__ void mma_tf32(uint32_t d, uint64_t a, uint64_t b, uint32_t id, uint32_t en){
    asm volatile("{\n\t.reg .pred p;\n\tsetp.ne.u32 p,%5,0;\n\ttcgen05.mma.cta_group::1.kind::tf32 [%0],%1,%2,%3,{%4,%4,%4,%4},p;\n\t}"
        ::"r"(d),"l"(a),"l"(b),"r"(id),"r"(0u),"r"(en):"memory");
}
__device__ __forceinline__ void bulk_cp(uint32_t dst, const uint32_t* src, uint32_t bytes, uint32_t mb){
    uint64_t g; asm("cvta.to.global.u64 %0, %1;":"=l"(g):"l"(src));
    asm volatile("cp.async.bulk.shared::cluster.global.mbarrier::complete_tx::bytes [%0],[%1],%2,[%3];"
        ::"r"(dst),"l"(g),"r"(bytes),"r"(mb):"memory");
}
__device__ __forceinline__ void issue_load(uint32_t sb, int i){
    const uint32_t* src = g_w2[i & 15];
    uint32_t mb = sb + SO_MBF + 8u*((uint32_t)i&1u);
    uint32_t dst = sb + SO_B + (uint32_t)(i&1)*32768u;
    asm volatile("mbarrier.arrive.expect_tx.shared.b64 _,[%0],%1;"::"r"(mb),"r"(32768u):"memory");
    bulk_cp(dst, src, 16384u, mb);
    bulk_cp(dst + 16384u, src + 4096, 16384u, mb);
}
#define LDTM16(r, addr) asm volatile( \
    "tcgen05.ld.sync.aligned.32x32b.x16.b32 {%0,%1,%2,%3,%4,%5,%6,%7,%8,%9,%10,%11,%12,%13,%14,%15}, [%16];" \
    : "=r"(r[0]),"=r"(r[1]),"=r"(r[2]),"=r"(r[3]),"=r"(r[4]),"=r"(r[5]),"=r"(r[6]),"=r"(r[7]), \
      "=r"(r[8]),"=r"(r[9]),"=r"(r[10]),"=r"(r[11]),"=r"(r[12]),"=r"(r[13]),"=r"(r[14]),"=r"(r[15]) : "r"(addr))
#endif // HAS_TC

// ---------------- weight prep (w2 K=16 tiles, SW64, 64B rows) ----------------
__global__ __launch_bounds__(256) void prep_w2(const float* __restrict__ w2){
    int i = blockIdx.x*256 + threadIdx.x;            // 65536
    int t = i>>12, r = i&4095, n = r>>4, k = r&15;
    float v = w2[(t*16+k)*256+n];
    uint32_t hi, lo; split_tf32(v, hi, lo);
    uint32_t s = swz64((uint32_t)n*64u + (uint32_t)k*4u) >> 2;
    g_w2[t][s] = hi; g_w2[t][4096+s] = lo;
}

// ---------------- proposal --------------------------------------------------
__global__ __launch_bounds__(256) void proposal_kernel(
    const float* __restrict__ state, const float* __restrict__ proprio,
    const float* __restrict__ noise,
    const float* __restrict__ pw1, const float* __restrict__ pb1,
    const float* __restrict__ pw2, const float* __restrict__ pb2)
{
    int warp = threadIdx.x>>5, lane = threadIdx.x&31;
    int b = blockIdx.x*8 + warp;
    float h[8];
#pragma unroll
    for (int c=0;c<8;c++) h[c] = pb1[lane+32*c];
#pragma unroll
    for (int i=0;i<11;i++){
        float xi = (i<9) ? state[b*9+i] : proprio[b*2+(i-9)];
#pragma unroll
        for (int c=0;c<8;c++) h[c] = fmaf(xi, pw1[i*256+lane+32*c], h[c]);
    }
#pragma unroll
    for (int c=0;c<8;c++) h[c] = fmaxf(h[c], 0.0f);
    float p[7];
#pragma unroll
    for (int a=0;a<7;a++){
        float s = 0.0f;
#pragma unroll
        for (int c=0;c<8;c++) s = fmaf(h[c], pw2[(lane+32*c)*7+a], s);
        p[a] = s;
    }
#pragma unroll
    for (int off=16;off>=1;off>>=1)
#pragma unroll
        for (int a=0;a<7;a++) p[a] += __shfl_xor_sync(0xffffffffu, p[a], off);
    if (lane < 7){
        float base = tanhf(p[lane] + pb2[lane]);
#pragma unroll
        for (int s=0;s<SSAMP;s++){
            float v = base + 0.2f*noise[(s*BB+b)*7+lane];
            g_cand[(s*BB+b)*7+lane] = fminf(fmaxf(v,-1.0f),1.0f);
        }
    }
}

// ---- tc rollout: G2 on tcgen05 (K=16 tiles), G1+G3 on FP32, 2 CTAs/SM ------
__global__ __launch_bounds__(256,2) void rollout_tc(
    const float* __restrict__ state, const float* __restrict__ target,
    const float* __restrict__ b1g, const float* __restrict__ b2g,
    const float* __restrict__ b3g, const float* __restrict__ w3g,
    const float* __restrict__ w1g)
{
#if HAS_TC
    extern __shared__ char sm[];
    const uint32_t sb = smem_u32(sm);
    const int tid = threadIdx.x, wid = tid>>5;
    const int wg = tid >> 7;          // warpgroup: j-half of each chunk
    const int wt = tid & 127;         // row within CTA (TMEM lane)
    const int s_idx = blockIdx.x >> 6;
    const int gb = ((blockIdx.x & 63) << 7) + wt;

    if (wid==0){
        asm volatile("tcgen05.alloc.cta_group::1.sync.aligned.shared::cta.b32 [%0],%1;"::"r"(sb+SO_TM),"r"(256u):"memory");
        asm volatile("tcgen05.relinquish_alloc_permit.cta_group::1.sync.aligned;":::"memory");
    }
    if (tid==0){
#pragma unroll
        for (int j=0;j<2;j++){
            asm volatile("mbarrier.init.shared.b64 [%0],1;"::"r"(sb+SO_MBF+8u*j):"memory");
            asm volatile("mbarrier.init.shared.b64 [%0],1;"::"r"(sb+SO_MBD+8u*j):"memory");
        }
    }
    float* s_b1  = (float*)(sm+SO_B1);
    float* s_b2  = (float*)(sm+SO_B2);
    float* s_w3  = (float*)(sm+SO_W3);
    float* s_w1  = (float*)(sm+SO_W1);
    float* s_sim = (float*)(sm+SO_SIM);
    float* s_pt  = (float*)(sm+SO_A);      // overlay: valid only in epilogue
    s_b1[tid] = b1g[tid];
    s_b2[tid] = b2g[tid];
    for (int i=tid; i<2304; i+=256) s_w3[i] = w3g[i];
    for (int i=tid; i<4096; i+=256) s_w1[i] = w1g[i];

    // per-row regs
    float tg[3]; float b3r[9]; float cost = 0.0f;
    float inp[16];
#pragma unroll
    for (int a=0;a<7;a++) inp[9+a] = g_cand[(s_idx*BB+gb)*7+a];
#pragma unroll
    for (int d=0;d<9;d++) inp[d] = state[gb*9+d];
    if (wg==0){
        tg[0]=target[gb*3+0]; tg[1]=target[gb*3+1]; tg[2]=target[gb*3+2];
#pragma unroll
        for (int d=0;d<9;d++) b3r[d] = b3g[d];
    }
    __syncthreads();

    uint32_t tmem;
    asm volatile("ld.shared.b32 %0,[%1];":"=r"(tmem):"r"(sb+SO_TM));

    if (wid==0 && elect_one()) issue_load(sb, 0);

    for (int step=0; step<HOR; step++){
        const int i0 = step*16;
        for (int lay=0; lay<16; lay++){
            const int i = i0+lay;
            // ---- compute h1 chunk on FP32 pipe (independent of waits) ----
            const int J = lay*16 + wg*8;
            float h[8];
#pragma unroll
            for (int jj=0;jj<8;jj++) h[jj] = s_b1[J+jj];
#pragma unroll
            for (int k=0;k<16;k++){
                F4 wA = ld4s(s_w1 + k*256 + J);
                F4 wB = ld4s(s_w1 + k*256 + J + 4);
#pragma unroll
                for (int jj=0;jj<4;jj++){
                    h[jj]   = fmaf(inp[k], wA.v[jj], h[jj]);
                    h[4+jj] = fmaf(inp[k], wB.v[jj], h[4+jj]);
                }
            }
            uint32_t hi[8], lo[8];
#pragma unroll
            for (int jj=0;jj<8;jj++) split_tf32(fmaxf(h[jj],0.0f), hi[jj], lo[jj]);

            // ---- A-slot + B-slot guard (lay 0 covered by epilogue wait) ----
            if (lay > 0) WAIT_DONE(i-1);
            // store into single A slot (SW64, 64B rows)
            {
                char* ah = sm + SO_A;
                char* al = ah + 8192;
                uint32_t ro = (uint32_t)wt * 64u + (uint32_t)wg * 32u;
#pragma unroll
                for (int g=0; g<2; g++){
                    uint32_t byte = ro + (uint32_t)g*16u;
                    uint32_t sw = byte ^ ((byte>>3)&0x30u);
                    *reinterpret_cast<uint4*>(ah+sw) = make_uint4(hi[4*g],hi[4*g+1],hi[4*g+2],hi[4*g+3]);
                    *reinterpret_cast<uint4*>(al+sw) = make_uint4(lo[4*g],lo[4*g+1],lo[4*g+2],lo[4*g+3]);
                }
            }
            FENCE_ASYNC();
            __syncthreads();

            if (wid==0 && elect_one()){
                if (i+1 < NT) issue_load(sb, i+1);  // slot (i+1)&1 freed by done(i-1)
                WAIT_FULL(i);
                uint64_t aH = sdesc64(sb + SO_A), aL = sdesc64(sb + SO_A + 8192u);
                uint32_t bAddr = sb + SO_B + (uint32_t)(i&1)*32768u;
                uint64_t bH = sdesc64(bAddr), bL = sdesc64(bAddr + 16384u);
#pragma unroll
                for (int q=0;q<2;q++){
                    uint64_t ao = (uint64_t)q*2u, bo = (uint64_t)q*2u;
                    uint32_t en0 = (lay==0 && q==0) ? 0u : 1u;
                    mma_tf32(tmem, aH+ao, bH+bo, IDESC_N256, en0);
                    mma_tf32(tmem, aH+ao, bL+bo, IDESC_N256, 1u);
                    mma_tf32(tmem, aL+ao, bH+bo, IDESC_N256, 1u);
                }
                asm volatile("tcgen05.commit.cta_group::1.mbarrier::arrive::one.shared::cluster.b64 [%0];"
                    ::"r"(sb+SO_MBD+8u*((uint32_t)i&1u)):"memory");
            }
        }

        // ======== epilogue: G3 on FP32: sim = relu(D2+b2) @ w3 + b3 ========
        {
            WAIT_DONE(i0+15); FENCE_AFTER();
            float pd[9];
#pragma unroll
            for (int d=0;d<9;d++) pd[d] = 0.0f;
#pragma unroll
            for (int c=0;c<8;c++){
                const int base = wg*128 + c*16;
                uint32_t r[16]; LDTM16(r, tmem + (uint32_t)base); TM_WAIT_LD();
#pragma unroll
                for (int j=0;j<16;j++){
                    float x = fmaxf(__uint_as_float(r[j]) + s_b2[base+j], 0.0f);
                    const float* wr = s_w3 + (base+j)*9;
#pragma unroll
                    for (int d=0;d<9;d++) pd[d] = fmaf(x, wr[d], pd[d]);
                }
            }
            __syncthreads();           // A slot fully consumed; safe to overlay s_pt
            if (wg==1){
#pragma unroll
                for (int d=0;d<9;d++) s_pt[wt*9+d] = pd[d];
            }
            __syncthreads();
            if (wg==0){
#pragma unroll
                for (int d=0;d<9;d++){
                    float sv = pd[d] + s_pt[wt*9+d] + b3r[d];
                    s_sim[wt*9+d] = sv;
                }
#pragma unroll
                for (int d=0;d<3;d++){ float t = s_sim[wt*9+d]-tg[d]; cost = fmaf(t,t,cost); }
            }
            __syncthreads();
#pragma unroll
            for (int d=0;d<9;d++) inp[d] = s_sim[wt*9+d];
            __syncthreads();           // everyone read s_sim; next step may proceed
        }
    }

    if (wg==0) g_cost[s_idx*BB + gb] = cost;
    __syncthreads();
    if (wid==0){
        asm volatile("tcgen05.dealloc.cta_group::1.sync.aligned.b32 %0,%1;"::"r"(tmem),"r"(256u));
    }
#endif // HAS_TC
}

// ---------------- FFMA fallback rollout (non-'a' targets) -------------------
__global__ __launch_bounds__(256, 1) void rollout_fb(
    const float* __restrict__ state, const float* __restrict__ target,
    const float* __restrict__ w1, const float* __restrict__ b1,
    const float* __restrict__ w2, const float* __restrict__ b2,
    const float* __restrict__ w3, const float* __restrict__ b3)
{
#if !HAS_TC
    extern __shared__ float smem[];
    float* s_w1  = smem;
    float* s_b1  = s_w1 + 4096;
    float* s_b2  = s_b1 + 256;
    float* s_w3t = s_b2 + 256;
    float* s_b3  = s_w3t + 2304;
    float* s_tgt = s_b3 + 16;
    float* s_inp = s_tgt + 192;
    float* s_h   = s_inp + 1024;
    float* s_wt  = s_h + 16384;

    const int tid = threadIdx.x;
    const int sample0 = blockIdx.x * TILE_M;
    const int s_idx = sample0 / BB;
    const int b0 = sample0 % BB;

    {
        const float4* src = reinterpret_cast<const float4*>(w2);
        float4* dst = reinterpret_cast<float4*>(s_wt);
#pragma unroll
        for (int i = 0; i < 8; i++) {
            int idx = tid + i * 256;
            cp16(reinterpret_cast<float*>(dst + idx),
                 reinterpret_cast<const float*>(src + idx));
        }
        cp_commit();
    }
    {
        const float4* w1v = reinterpret_cast<const float4*>(w1);
        float4* sw1v = reinterpret_cast<float4*>(s_w1);
        for (int i = tid; i < 1024; i += 256) sw1v[i] = w1v[i];
        s_b1[tid] = b1[tid];
        s_b2[tid] = b2[tid];
        for (int i = tid; i < 2304; i += 256) {
            int j = i / 9, d = i % 9;
            s_w3t[d * 256 + j] = w3[i];
        }
        if (tid < 9) s_b3[tid] = b3[tid];
        if (tid < 192) s_tgt[tid] = target[b0 * 3 + tid];
        for (int i = tid; i < 576; i += 256) {
            int m = i / 9, d = i % 9;
            s_inp[m * 16 + d] = state[(b0 + m) * 9 + d];
        }
        for (int i = tid; i < 448; i += 256) {
            int m = i / 7, a = i % 7;
            s_inp[m * 16 + 9 + a] = g_cand[(s_idx * BB + b0 + m) * 7 + a];
        }
    }
    __syncthreads();

    const int mi = tid >> 5;
    const int ji = tid & 31;
    const int J0 = ji * 4;
    const int J1 = 128 + ji * 4;
    const int mrow = mi * 8;

    float cm[8];
#pragma unroll
    for (int mm = 0; mm < 8; mm++) cm[mm] = 0.0f;
    u64 accp[8][4];
    int cur = 0;

    for (int step = 0; step < HOR; step++) {
        {
            ulonglong2 bA = *reinterpret_cast<const ulonglong2*>(s_b1 + J0);
            ulonglong2 bB = *reinterpret_cast<const ulonglong2*>(s_b1 + J1);
#pragma unroll
            for (int mm = 0; mm < 8; mm++) {
                accp[mm][0] = bA.x; accp[mm][1] = bA.y;
                accp[mm][2] = bB.x; accp[mm][3] = bB.y;
            }
#pragma unroll 2
            for (int k0 = 0; k0 < 16; k0 += 4) {
                ulonglong2 wA2[4], wB2[4];
#pragma unroll
                for (int t = 0; t < 4; t++) {
                    wA2[t] = *reinterpret_cast<const ulonglong2*>(s_w1 + (k0 + t) * 256 + J0);
                    wB2[t] = *reinterpret_cast<const ulonglong2*>(s_w1 + (k0 + t) * 256 + J1);
                }
#pragma unroll
                for (int mm = 0; mm < 8; mm++) {
                    F4 iv = ld4s(s_inp + (mrow + mm) * 16 + k0);
#pragma unroll
                    for (int t = 0; t < 4; t++) {
                        u64 hd = dup2f(iv.v[t]);
                        fma2(accp[mm][0], hd, wA2[t].x);
                        fma2(accp[mm][1], hd, wA2[t].y);
                        fma2(accp[mm][2], hd, wB2[t].x);
                        fma2(accp[mm][3], hd, wB2[t].y);
                    }
                }
            }
#pragma unroll
            for (int mm = 0; mm < 8; mm++) {
                float2 a0 = unpk(accp[mm][0]), a1 = unpk(accp[mm][1]);
                float2 a2 = unpk(accp[mm][2]), a3 = unpk(accp[mm][3]);
                float4 st0, st1;
                st0.x = fmaxf(a0.x, 0.0f); st0.y = fmaxf(a0.y, 0.0f);
                st0.z = fmaxf(a1.x, 0.0f); st0.w = fmaxf(a1.y, 0.0f);
                st1.x = fmaxf(a2.x, 0.0f); st1.y = fmaxf(a2.y, 0.0f);
                st1.z = fmaxf(a3.x, 0.0f); st1.w = fmaxf(a3.y, 0.0f);
                *reinterpret_cast<float4*>(&s_h[(mrow + mm) * 256 + J0]) = st0;
                *reinterpret_cast<float4*>(&s_h[(mrow + mm) * 256 + J1]) = st1;
            }
        }
        {
            ulonglong2 bA = *reinterpret_cast<const ulonglong2*>(s_b2 + J0);
            ulonglong2 bB = *reinterpret_cast<const ulonglong2*>(s_b2 + J1);
#pragma unroll
            for (int mm = 0; mm < 8; mm++) {
                accp[mm][0] = bA.x; accp[mm][1] = bA.y;
                accp[mm][2] = bB.x; accp[mm][3] = bB.y;
            }
            for (int kt = 0; kt < 8; kt++) {
                int nxt = cur + 1; if (nxt == 3) nxt = 0;
                bool more = (kt < 7) || (step < HOR - 1);
                if (more) {
                    int ntile = (kt + 1) & 7;
                    const float4* src = reinterpret_cast<const float4*>(w2 + ntile * KT * 256);
                    float4* dst = reinterpret_cast<float4*>(s_wt + nxt * 8192);
#pragma unroll
                    for (int i = 0; i < 8; i++) {
                        int idx = tid + i * 256;
                        cp16(reinterpret_cast<float*>(dst + idx),
                             reinterpret_cast<const float*>(src + idx));
                    }
                    cp_commit();
                    cp_wait1();
                } else {
                    cp_wait0();
                }
                __syncthreads();

                const float* W = s_wt + cur * 8192;
                const float* Hbase = s_h + mrow * 256 + kt * KT;
#pragma unroll 2
                for (int kk = 0; kk < KT; kk += 4) {
                    ulonglong2 wA2[4], wB2[4];
#pragma unroll
                    for (int t = 0; t < 4; t++) {
                        wA2[t] = *reinterpret_cast<const ulonglong2*>(W + (kk + t) * 256 + J0);
                        wB2[t] = *reinterpret_cast<const ulonglong2*>(W + (kk + t) * 256 + J1);
                    }
#pragma unroll
                    for (int mm = 0; mm < 8; mm++) {
                        F4 hv = ld4s(Hbase + mm * 256 + kk);
#pragma unroll
                        for (int t = 0; t < 4; t++) {
                            u64 hd = dup2f(hv.v[t]);
                            fma2(accp[mm][0], hd, wA2[t].x);
                            fma2(accp[mm][1], hd, wA2[t].y);
                            fma2(accp[mm][2], hd, wB2[t].x);
                            fma2(accp[mm][3], hd, wB2[t].y);
                        }
                    }
                }
                cur = nxt;
            }
        }
        {
#pragma unroll
            for (int mm = 0; mm < 8; mm++)
#pragma unroll
                for (int p = 0; p < 4; p++) accp[mm][p] = relu2(accp[mm][p]);

            for (int d = 0; d < 9; d++) {
                ulonglong2 wA2 = *reinterpret_cast<const ulonglong2*>(s_w3t + d * 256 + J0);
                ulonglong2 wB2 = *reinterpret_cast<const ulonglong2*>(s_w3t + d * 256 + J1);
                float pd[8];
#pragma unroll
                for (int mm = 0; mm < 8; mm++) {
                    u64 p = 0ULL;
                    fma2(p, accp[mm][0], wA2.x);
                    fma2(p, accp[mm][1], wA2.y);
                    fma2(p, accp[mm][2], wB2.x);
                    fma2(p, accp[mm][3], wB2.y);
                    float2 f = unpk(p);
                    pd[mm] = f.x + f.y;
                }
#pragma unroll
                for (int off = 16; off >= 1; off >>= 1) {
#pragma unroll
                    for (int mm = 0; mm < 8; mm++)
                        pd[mm] += __shfl_xor_sync(0xffffffffu, pd[mm], off);
                }
                if (ji == 0) {
#pragma unroll
                    for (int mm = 0; mm < 8; mm++) {
                        float sv = pd[mm] + s_b3[d];
                        s_inp[(mrow + mm) * 16 + d] = sv;
                        if (d < 3) {
                            float t = sv - s_tgt[(mrow + mm) * 3 + d];
                            cm[mm] = fmaf(t, t, cm[mm]);
                        }
                    }
                }
            }
            __syncwarp();
        }
    }

    if (ji == 0) {
#pragma unroll
        for (int mm = 0; mm < 8; mm++)
            g_cost[s_idx * BB + b0 + mrow + mm] = cm[mm];
    }
#endif // !HAS_TC
}

// ---------------- select ----------------------------------------------------
__global__ __launch_bounds__(256) void select_kernel(float* __restrict__ out)
{
    int b = blockIdx.x*blockDim.x + threadIdx.x;
    if (b >= BB) return;
    float best = g_cost[b]; int bi = 0;
#pragma unroll
    for (int s=1;s<SSAMP;s++){
        float c = g_cost[s*BB+b];
        if (c < best){ best = c; bi = s; }
    }
    const float* src = g_cand + (bi*BB+b)*7;
#pragma unroll
    for (int a=0;a<7;a++) out[b*7+a] = src[a];
}

// ---------------- launch -----------------------------------------------------
extern "C" void kernel_launch(void* const* d_in, const int* in_sizes, int n_in,
                              void* d_out, int out_size)
{
    (void)in_sizes; (void)n_in; (void)out_size;
    const float* state   = (const float*)d_in[0];
    const float* proprio = (const float*)d_in[1];
    const float* target  = (const float*)d_in[2];
    const float* noise   = (const float*)d_in[3];
    const float* pw1 = (const float*)d_in[4];
    const float* pb1 = (const float*)d_in[5];
    const float* pw2 = (const float*)d_in[6];
    const float* pb2 = (const float*)d_in[7];
    const float* w1  = (const float*)d_in[8];
    const float* b1  = (const float*)d_in[9];
    const float* w2  = (const float*)d_in[10];
    const float* b2  = (const float*)d_in[11];
    const float* w3  = (const float*)d_in[12];
    const float* b3  = (const float*)d_in[13];
    float* out = (float*)d_out;

    cudaFuncSetAttribute(rollout_tc, cudaFuncAttributeMaxDynamicSharedMemorySize, SMEMSZ);
    cudaFuncSetAttribute(rollout_fb, cudaFuncAttributeMaxDynamicSharedMemorySize, FB_BYTES);

    prep_w2<<<256, 256>>>(w2);
    proposal_kernel<<<BB/8, 256>>>(state, proprio, noise, pw1, pb1, pw2, pb2);
    rollout_tc<<<(SSAMP*BB)/128, 256, SMEMSZ>>>(state, target, b1, b2, b3, w3, w1);
    rollout_fb<<<(SSAMP*BB)/TILE_M, 256, FB_BYTES>>>(state, target, w1, b1, w2, b2, w3, b3);
    select_kernel<<<BB/256, 256>>>(out);
}

// round 16
// speedup vs baseline: 1.1328x; 1.1328x over previous
#include <cuda_runtime.h>
#include <cstdint>

#define BB 8192
#define SSAMP 8
#define HOR 4
#define NT 36   // 4 steps * (1 G1 + 8 G2) tiles; G3 runs on the FP32 pipe
#define TILE_M 64
#define KT 32

#if defined(__CUDA_ARCH__) && (defined(__CUDA_ARCH_FEAT_SM103_ALL) || defined(__CUDA_ARCH_FEAT_SM100_ALL) || defined(__CUDA_ARCH_SPECIFIC__))
#define HAS_TC 1
#else
#define HAS_TC 0
#endif

// idesc: F32 accum (1<<4) | atype TF32 (2<<7) | btype TF32 (2<<10) | (N/8)<<17 | (M/16)<<24
#define IDESC_N256 ((1u<<4)|(2u<<7)|(2u<<10)|(32u<<17)|(8u<<24))

// tc smem byte offsets
#define SO_TM   0
#define SO_MBF  16
#define SO_MBD  32
#define SO_B1   64        // 256 f
#define SO_B2   1088      // 256 f
#define SO_W3   2112      // 2304 f  (w3 row-major [256][9])
#define SO_PART 11328     // 128*9 f (wg1 partial sums)
#define SO_A    16384     // A slot s: hi @ +s*32768, lo @ hi+16384 (2 slots)
#define SO_B    81920     // B slot s: hi @ +s*65536, lo @ +32768   (2 slots)
#define SMEMSZ  212992

// fb smem
#define FB_FLOATS 49104
#define FB_BYTES  (FB_FLOATS * 4)

typedef unsigned long long u64;

__device__ float g_cand[SSAMP*BB*7];
__device__ float g_cost[SSAMP*BB];
// prepped weights: SW128-swizzled K-major tf32 tiles, [hi block][lo block]
__device__ __align__(128) uint32_t g_w1[2*8192];
__device__ __align__(128) uint32_t g_w2[8][2*8192];

// ------------------------- shared helpers ----------------------------------
__device__ __forceinline__ void split_tf32(float v, uint32_t& hi, uint32_t& lo){
    asm("cvt.rna.tf32.f32 %0, %1;":"=r"(hi):"f"(v));
    float r = v - __uint_as_float(hi);
    asm("cvt.rna.tf32.f32 %0, %1;":"=r"(lo):"f"(r));
}
__device__ __forceinline__ uint32_t swz(uint32_t b){ return b ^ ((b>>3)&0x70u); }

struct F4 { float v[4]; };
__device__ __forceinline__ F4 ld4s(const float* p){
    float4 t = *reinterpret_cast<const float4*>(p);
    F4 r; r.v[0]=t.x; r.v[1]=t.y; r.v[2]=t.z; r.v[3]=t.w; return r;
}
__device__ __forceinline__ u64 dup2f(float x){
    u64 r; asm("mov.b64 %0, {%1, %2};" : "=l"(r) : "f"(x), "f"(x)); return r;
}
__device__ __forceinline__ void fma2(u64& d, u64 a, u64 b){
    asm("fma.rn.f32x2 %0, %1, %2, %3;" : "=l"(d) : "l"(a), "l"(b), "l"(d));
}
__device__ __forceinline__ float2 unpk(u64 x){
    float2 f; asm("mov.b64 {%0, %1}, %2;" : "=f"(f.x), "=f"(f.y) : "l"(x)); return f;
}
__device__ __forceinline__ u64 relu2(u64 x){
    float2 f = unpk(x);
    f.x = fmaxf(f.x, 0.0f); f.y = fmaxf(f.y, 0.0f);
    u64 r; asm("mov.b64 %0, {%1, %2};" : "=l"(r) : "f"(f.x), "f"(f.y)); return r;
}
__device__ __forceinline__ void cp16(float* smem_dst, const float* gsrc){
    uint32_t d = (uint32_t)__cvta_generic_to_shared(smem_dst);
    asm volatile("cp.async.cg.shared.global [%0], [%1], 16;\n" :: "r"(d), "l"(gsrc));
}
__device__ __forceinline__ void cp_commit(){ asm volatile("cp.async.commit_group;\n" ::); }
__device__ __forceinline__ void cp_wait1(){ asm volatile("cp.async.wait_group 1;\n" ::); }
__device__ __forceinline__ void cp_wait0(){ asm volatile("cp.async.wait_group 0;\n" ::); }

// ------------------------- tc-only helpers ---------------------------------
#if HAS_TC
__device__ __forceinline__ uint32_t smem_u32(const void* p){
    uint32_t a; asm("{ .reg .u64 t; cvta.to.shared.u64 t, %1; cvt.u32.u64 %0, t; }":"=r"(a):"l"(p)); return a;
}
__device__ __forceinline__ uint32_t elect_one(){
    uint32_t p; asm volatile("{ .reg .pred q; elect.sync _|q, 0xFFFFFFFF; selp.b32 %0,1,0,q; }":"=r"(p)); return p;
}
__device__ __forceinline__ uint64_t sdesc(uint32_t a){ // SW128, LBO=1, SBO=64, v1
    return ((uint64_t)2<<61)|((uint64_t)1<<46)|((uint64_t)64<<32)|((uint64_t)1<<16)|((uint64_t)(a>>4)&0x3FFF);
}
__device__ __forceinline__ void wait_par(uint32_t mb, uint32_t par){
    asm volatile("{\n\t.reg .pred P;\nWL%=:\n\tmbarrier.try_wait.parity.acquire.cta.shared::cta.b64 P,[%0],%1,0x989680;\n\t@P bra.uni WD%=;\n\tbra.uni WL%=;\nWD%=:\n\t}"::"r"(mb),"r"(par):"memory");
}
#define WAIT_DONE(i) wait_par(sb+SO_MBD+8u*((uint32_t)(i)&1u), ((uint32_t)(i)>>1)&1u)
#define WAIT_FULL(i) wait_par(sb+SO_MBF+8u*((uint32_t)(i)&1u), ((uint32_t)(i)>>1)&1u)
#define FENCE_AFTER()  asm volatile("tcgen05.fence::after_thread_sync;":::"memory")
#define FENCE_ASYNC()  asm volatile("fence.proxy.async.shared::cta;":::"memory")
#define TM_WAIT_LD()   asm volatile("tcgen05.wait::ld.sync.aligned;":::"memory")

__device__ __forceinline__ void mma_tf32(uint32_t d, uint64_t a, uint64_t b, uint32_t id, uint32_t en){
    asm volatile("{\n\t.reg .pred p;\n\tsetp.ne.u32 p,%5,0;\n\ttcgen05.mma.cta_group::1.kind::tf32 [%0],%1,%2,%3,{%4,%4,%4,%4},p;\n\t}"
        ::"r"(d),"l"(a),"l"(b),"r"(id),"r"(0u),"r"(en):"memory");
}
__device__ __forceinline__ void bulk_cp(uint32_t dst, const uint32_t* src, uint32_t bytes, uint32_t mb){
    uint64_t g; asm("cvta.to.global.u64 %0, %1;":"=l"(g):"l"(src));
    asm volatile("cp.async.bulk.shared::cluster.global.mbarrier::complete_tx::bytes [%0],[%1],%2,[%3];"
        ::"r"(dst),"l"(g),"r"(bytes),"r"(mb):"memory");
}
__device__ __forceinline__ void issue_load(uint32_t sb, int i){
    int lay = i % 9;
    const uint32_t* src = (lay==0) ? g_w1 : g_w2[lay-1];
    uint32_t mb = sb + SO_MBF + 8u*((uint32_t)i&1u);
    uint32_t dst = sb + SO_B + (uint32_t)(i&1)*65536u;
    asm volatile("mbarrier.arrive.expect_tx.shared.b64 _,[%0],%1;"::"r"(mb),"r"(65536u):"memory");
    bulk_cp(dst, src, 65536u, mb);
}
#define LDTM16(r, addr) asm volatile( \
    "tcgen05.ld.sync.aligned.32x32b.x16.b32 {%0,%1,%2,%3,%4,%5,%6,%7,%8,%9,%10,%11,%12,%13,%14,%15}, [%16];" \
    : "=r"(r[0]),"=r"(r[1]),"=r"(r[2]),"=r"(r[3]),"=r"(r[4]),"=r"(r[5]),"=r"(r[6]),"=r"(r[7]), \
      "=r"(r[8]),"=r"(r[9]),"=r"(r[10]),"=r"(r[11]),"=r"(r[12]),"=r"(r[13]),"=r"(r[14]),"=r"(r[15]) : "r"(addr))
#endif // HAS_TC

// ---------------- weight prep --------------------------------------------
__global__ __launch_bounds__(256) void prep_w1(const float* __restrict__ w1){
    int i = blockIdx.x*256 + threadIdx.x;
    int n = i>>5, k = i&31;
    float v = (k<16) ? w1[k*256+n] : 0.0f;
    uint32_t hi, lo; split_tf32(v, hi, lo);
    uint32_t s = swz((uint32_t)n*128u + (uint32_t)k*4u) >> 2;
    g_w1[s] = hi; g_w1[8192+s] = lo;
}
__global__ __launch_bounds__(256) void prep_w2(const float* __restrict__ w2){
    int i = blockIdx.x*256 + threadIdx.x;
    int t = i>>13, r = i&8191, n = r>>5, k = r&31;
    float v = w2[(t*32+k)*256+n];
    uint32_t hi, lo; split_tf32(v, hi, lo);
    uint32_t s = swz((uint32_t)n*128u + (uint32_t)k*4u) >> 2;
    g_w2[t][s] = hi; g_w2[t][8192+s] = lo;
}

// ---------------- proposal --------------------------------------------------
__global__ __launch_bounds__(256) void proposal_kernel(
    const float* __restrict__ state, const float* __restrict__ proprio,
    const float* __restrict__ noise,
    const float* __restrict__ pw1, const float* __restrict__ pb1,
    const float* __restrict__ pw2, const float* __restrict__ pb2)
{
    int warp = threadIdx.x>>5, lane = threadIdx.x&31;
    int b = blockIdx.x*8 + warp;
    float h[8];
#pragma unroll
    for (int c=0;c<8;c++) h[c] = pb1[lane+32*c];
#pragma unroll
    for (int i=0;i<11;i++){
        float xi = (i<9) ? state[b*9+i] : proprio[b*2+(i-9)];
#pragma unroll
        for (int c=0;c<8;c++) h[c] = fmaf(xi, pw1[i*256+lane+32*c], h[c]);
    }
#pragma unroll
    for (int c=0;c<8;c++) h[c] = fmaxf(h[c], 0.0f);
    float p[7];
#pragma unroll
    for (int a=0;a<7;a++){
        float s = 0.0f;
#pragma unroll
        for (int c=0;c<8;c++) s = fmaf(h[c], pw2[(lane+32*c)*7+a], s);
        p[a] = s;
    }
#pragma unroll
    for (int off=16;off>=1;off>>=1)
#pragma unroll
        for (int a=0;a<7;a++) p[a] += __shfl_xor_sync(0xffffffffu, p[a], off);
    if (lane < 7){
        float base = tanhf(p[lane] + pb2[lane]);
#pragma unroll
        for (int s=0;s<SSAMP;s++){
            float v = base + 0.2f*noise[(s*BB+b)*7+lane];
            g_cand[(s*BB+b)*7+lane] = fminf(fmaxf(v,-1.0f),1.0f);
        }
    }
}

// ---- tensor-core rollout: register-pipelined staging, back-to-back MMAs ----
__global__ __launch_bounds__(256,1) void rollout_tc(
    const float* __restrict__ state, const float* __restrict__ target,
    const float* __restrict__ b1g, const float* __restrict__ b2g,
    const float* __restrict__ b3g, const float* __restrict__ w3g)
{
#if HAS_TC
    extern __shared__ char sm[];
    const uint32_t sb = smem_u32(sm);
    const int tid = threadIdx.x, wid = tid>>5;
    const int wg = tid >> 7;          // warpgroup 0/1 (stage col halves)
    const int wt = tid & 127;         // row within CTA (TMEM lane)
    const int s_idx = blockIdx.x >> 6;
    const int gb = ((blockIdx.x & 63) << 7) + wt;

    if (wid==0){
        asm volatile("tcgen05.alloc.cta_group::1.sync.aligned.shared::cta.b32 [%0],%1;"::"r"(sb+SO_TM),"r"(512u):"memory");
        asm volatile("tcgen05.relinquish_alloc_permit.cta_group::1.sync.aligned;":::"memory");
    }
    if (tid==0){
#pragma unroll
        for (int j=0;j<2;j++){
            asm volatile("mbarrier.init.shared.b64 [%0],1;"::"r"(sb+SO_MBF+8u*j):"memory");
            asm volatile("mbarrier.init.shared.b64 [%0],1;"::"r"(sb+SO_MBD+8u*j):"memory");
        }
    }
    float* s_b1 = (float*)(sm+SO_B1);
    float* s_b2 = (float*)(sm+SO_B2);
    float* s_w3 = (float*)(sm+SO_W3);
    float* s_pt = (float*)(sm+SO_PART);
    s_b1[tid] = b1g[tid];
    s_b2[tid] = b2g[tid];
    for (int i=tid; i<2304; i+=256) s_w3[i] = w3g[i];
    __syncthreads();

    uint32_t tmem;
    asm volatile("ld.shared.b32 %0,[%1];":"=r"(tmem):"r"(sb+SO_TM));

    float tg[3]; float b3r[9]; float sim[9]; float cost = 0.0f;
    uint32_t chi[7], clo[7];
    if (wg==0){
        tg[0]=target[gb*3+0]; tg[1]=target[gb*3+1]; tg[2]=target[gb*3+2];
#pragma unroll
        for (int d=0;d<9;d++) b3r[d] = b3g[d];
#pragma unroll
        for (int a=0;a<7;a++) split_tf32(g_cand[(s_idx*BB+gb)*7+a], chi[a], clo[a]);
#pragma unroll
        for (int d=0;d<9;d++) sim[d] = state[gb*9+d];
    }

    if (wid==0 && elect_one()) issue_load(sb, 0);

    #define STS_CHUNK(i_, H_, L_) do { \
        char* ah = sm + SO_A + ((i_)&1)*32768; \
        char* al = ah + 16384; \
        uint32_t ro = (uint32_t)wt * 128u + (uint32_t)wg * 64u; \
        _Pragma("unroll") \
        for (int g=0; g<4; g++){ \
            uint32_t byte = ro + (uint32_t)g*16u; \
            uint32_t sw = byte ^ ((byte>>3)&0x70u); \
            *reinterpret_cast<uint4*>(ah+sw) = make_uint4((H_)[4*g],(H_)[4*g+1],(H_)[4*g+2],(H_)[4*g+3]); \
            *reinterpret_cast<uint4*>(al+sw) = make_uint4((L_)[4*g],(L_)[4*g+1],(L_)[4*g+2],(L_)[4*g+3]); \
        } \
    } while(0)

    #define ISSUE_TILE(i_, dt_, nq_, gf_) do { \
        WAIT_FULL(i_); \
        uint32_t aAddr = sb + SO_A + (uint32_t)((i_)&1)*32768u; \
        uint32_t bAddr = sb + SO_B + (uint32_t)((i_)&1)*65536u; \
        uint64_t aH = sdesc(aAddr), aL = sdesc(aAddr+16384u); \
        uint64_t bH = sdesc(bAddr), bL = sdesc(bAddr+32768u); \
        _Pragma("unroll") \
        for (int q=0;q<4;q++){ \
            if (q >= (nq_)) break; \
            uint64_t ao = (uint64_t)q*2u, bo = (uint64_t)q*2u; \
            uint32_t en0 = ((gf_) && q==0) ? 0u : 1u; \
            mma_tf32((dt_), aH+ao, bH+bo, IDESC_N256, en0); \
            mma_tf32((dt_), aH+ao, bL+bo, IDESC_N256, 1u); \
            mma_tf32((dt_), aL+ao, bH+bo, IDESC_N256, 1u); \
        } \
        asm volatile("tcgen05.commit.cta_group::1.mbarrier::arrive::one.shared::cluster.b64 [%0];" \
            ::"r"(sb+SO_MBD+8u*((uint32_t)(i_)&1u)):"memory"); \
    } while(0)

    #define PREP_CHUNK(c_, H_, L_) do { \
        const uint32_t cb_ = (uint32_t)(c_)*32u + (uint32_t)wg*16u; \
        const int bb_ = (c_)*32 + wg*16; \
        uint32_t rr_[16]; LDTM16(rr_, tmem + cb_); TM_WAIT_LD(); \
        _Pragma("unroll") \
        for (int j=0;j<16;j++){ \
            float x_ = fmaxf(__uint_as_float(rr_[j]) + s_b1[bb_+j], 0.0f); \
            split_tf32(x_, (H_)[j], (L_)[j]); \
        } \
    } while(0)

    uint32_t hi[16], lo[16], nhi[16], nlo[16];

    for (int step=0; step<HOR; step++){
        const int i0 = step*9;
        // ================= lay 0 (G1): stage from registers ================
        if (wg==0){
#pragma unroll
            for (int j=0;j<9;j++) split_tf32(sim[j], hi[j], lo[j]);
#pragma unroll
            for (int a=0;a<7;a++){ hi[9+a]=chi[a]; lo[9+a]=clo[a]; }
        } else {
#pragma unroll
            for (int j=0;j<16;j++){ hi[j]=0u; lo[j]=0u; }
        }
        STS_CHUNK(i0, hi, lo);
        FENCE_ASYNC();
        __syncthreads();
        if (wid==0 && elect_one()){
            ISSUE_TILE(i0, tmem, 2, 1);
            if (i0+1 < NT) issue_load(sb, i0+1);
        }

        // ================= lay 1 (first G2): boundary =====================
        {
            const int i = i0+1;
            WAIT_DONE(i0); FENCE_AFTER();
            PREP_CHUNK(0, hi, lo);
            STS_CHUNK(i, hi, lo);
            FENCE_ASYNC();
            __syncthreads();
            if (wid==0 && elect_one()){
                ISSUE_TILE(i, tmem+256u, 4, 1);
                if (i+1 < NT) issue_load(sb, i+1);
            }
            PREP_CHUNK(1, nhi, nlo);
        }

        // ================= lay 2..8: register-pipelined ===================
        for (int lay=2; lay<=8; lay++){
            const int i = i0+lay;
            WAIT_DONE(i-2); FENCE_AFTER();
#pragma unroll
            for (int j=0;j<16;j++){ hi[j]=nhi[j]; lo[j]=nlo[j]; }
            STS_CHUNK(i, hi, lo);
            FENCE_ASYNC();
            __syncthreads();
            if (wid==0 && elect_one()){
                ISSUE_TILE(i, tmem+256u, 4, 0);
                WAIT_DONE(i-1);
                if (i+1 < NT) issue_load(sb, i+1);
            }
            if (lay < 8) PREP_CHUNK(lay, nhi, nlo);
        }

        // ======== epilogue: G3 on FP32 pipe: sim = relu(D2+b2) @ w3 + b3 ===
        {
            WAIT_DONE(i0+8); FENCE_AFTER();
            float pd[9];
#pragma unroll
            for (int d=0;d<9;d++) pd[d] = 0.0f;
#pragma unroll
            for (int c=0;c<8;c++){
                const int base = wg*128 + c*16;
                uint32_t r[16]; LDTM16(r, tmem + 256u + (uint32_t)base); TM_WAIT_LD();
#pragma unroll
                for (int j=0;j<16;j++){
                    float x = fmaxf(__uint_as_float(r[j]) + s_b2[base+j], 0.0f);
                    const float* wr = s_w3 + (base+j)*9;
#pragma unroll
                    for (int d=0;d<9;d++) pd[d] = fmaf(x, wr[d], pd[d]);
                }
            }
            if (wg==1){
#pragma unroll
                for (int d=0;d<9;d++) s_pt[wt*9+d] = pd[d];
            }
            __syncthreads();
            if (wg==0){
#pragma unroll
                for (int d=0;d<9;d++) sim[d] = pd[d] + s_pt[wt*9+d] + b3r[d];
#pragma unroll
                for (int d=0;d<3;d++){ float t = sim[d]-tg[d]; cost = fmaf(t,t,cost); }
            }
            __syncthreads();
        }
    }

    if (wg==0) g_cost[s_idx*BB + gb] = cost;
    __syncthreads();
    if (wid==0){
        asm volatile("tcgen05.dealloc.cta_group::1.sync.aligned.b32 %0,%1;"::"r"(tmem),"r"(512u));
    }
#endif // HAS_TC
}

// ---------------- FFMA fallback rollout (non-'a' targets) -------------------
__global__ __launch_bounds__(256, 1) void rollout_fb(
    const float* __restrict__ state, const float* __restrict__ target,
    const float* __restrict__ w1, const float* __restrict__ b1,
    const float* __restrict__ w2, const float* __restrict__ b2,
    const float* __restrict__ w3, const float* __restrict__ b3)
{
#if !HAS_TC
    extern __shared__ float smem[];
    float* s_w1  = smem;
    float* s_b1  = s_w1 + 4096;
    float* s_b2  = s_b1 + 256;
    float* s_w3t = s_b2 + 256;
    float* s_b3  = s_w3t + 2304;
    float* s_tgt = s_b3 + 16;
    float* s_inp = s_tgt + 192;
    float* s_h   = s_inp + 1024;
    float* s_wt  = s_h + 16384;

    const int tid = threadIdx.x;
    const int sample0 = blockIdx.x * TILE_M;
    const int s_idx = sample0 / BB;
    const int b0 = sample0 % BB;

    {
        const float4* src = reinterpret_cast<const float4*>(w2);
        float4* dst = reinterpret_cast<float4*>(s_wt);
#pragma unroll
        for (int i = 0; i < 8; i++) {
            int idx = tid + i * 256;
            cp16(reinterpret_cast<float*>(dst + idx),
                 reinterpret_cast<const float*>(src + idx));
        }
        cp_commit();
    }
    {
        const float4* w1v = reinterpret_cast<const float4*>(w1);
        float4* sw1v = reinterpret_cast<float4*>(s_w1);
        for (int i = tid; i < 1024; i += 256) sw1v[i] = w1v[i];
        s_b1[tid] = b1[tid];
        s_b2[tid] = b2[tid];
        for (int i = tid; i < 2304; i += 256) {
            int j = i / 9, d = i % 9;
            s_w3t[d * 256 + j] = w3[i];
        }
        if (tid < 9) s_b3[tid] = b3[tid];
        if (tid < 192) s_tgt[tid] = target[b0 * 3 + tid];
        for (int i = tid; i < 576; i += 256) {
            int m = i / 9, d = i % 9;
            s_inp[m * 16 + d] = state[(b0 + m) * 9 + d];
        }
        for (int i = tid; i < 448; i += 256) {
            int m = i / 7, a = i % 7;
            s_inp[m * 16 + 9 + a] = g_cand[(s_idx * BB + b0 + m) * 7 + a];
        }
    }
    __syncthreads();

    const int mi = tid >> 5;
    const int ji = tid & 31;
    const int J0 = ji * 4;
    const int J1 = 128 + ji * 4;
    const int mrow = mi * 8;

    float cm[8];
#pragma unroll
    for (int mm = 0; mm < 8; mm++) cm[mm] = 0.0f;
    u64 accp[8][4];
    int cur = 0;

    for (int step = 0; step < HOR; step++) {
        {
            ulonglong2 bA = *reinterpret_cast<const ulonglong2*>(s_b1 + J0);
            ulonglong2 bB = *reinterpret_cast<const ulonglong2*>(s_b1 + J1);
#pragma unroll
            for (int mm = 0; mm < 8; mm++) {
                accp[mm][0] = bA.x; accp[mm][1] = bA.y;
                accp[mm][2] = bB.x; accp[mm][3] = bB.y;
            }
#pragma unroll 2
            for (int k0 = 0; k0 < 16; k0 += 4) {
                ulonglong2 wA2[4], wB2[4];
#pragma unroll
                for (int t = 0; t < 4; t++) {
                    wA2[t] = *reinterpret_cast<const ulonglong2*>(s_w1 + (k0 + t) * 256 + J0);
                    wB2[t] = *reinterpret_cast<const ulonglong2*>(s_w1 + (k0 + t) * 256 + J1);
                }
#pragma unroll
                for (int mm = 0; mm < 8; mm++) {
                    F4 iv = ld4s(s_inp + (mrow + mm) * 16 + k0);
#pragma unroll
                    for (int t = 0; t < 4; t++) {
                        u64 hd = dup2f(iv.v[t]);
                        fma2(accp[mm][0], hd, wA2[t].x);
                        fma2(accp[mm][1], hd, wA2[t].y);
                        fma2(accp[mm][2], hd, wB2[t].x);
                        fma2(accp[mm][3], hd, wB2[t].y);
                    }
                }
            }
#pragma unroll
            for (int mm = 0; mm < 8; mm++) {
                float2 a0 = unpk(accp[mm][0]), a1 = unpk(accp[mm][1]);
                float2 a2 = unpk(accp[mm][2]), a3 = unpk(accp[mm][3]);
                float4 st0, st1;
                st0.x = fmaxf(a0.x, 0.0f); st0.y = fmaxf(a0.y, 0.0f);
                st0.z = fmaxf(a1.x, 0.0f); st0.w = fmaxf(a1.y, 0.0f);
                st1.x = fmaxf(a2.x, 0.0f); st1.y = fmaxf(a2.y, 0.0f);
                st1.z = fmaxf(a3.x, 0.0f); st1.w = fmaxf(a3.y, 0.0f);
                *reinterpret_cast<float4*>(&s_h[(mrow + mm) * 256 + J0]) = st0;
                *reinterpret_cast<float4*>(&s_h[(mrow + mm) * 256 + J1]) = st1;
            }
        }
        {
            ulonglong2 bA = *reinterpret_cast<const ulonglong2*>(s_b2 + J0);
            ulonglong2 bB = *reinterpret_cast<const ulonglong2*>(s_b2 + J1);
#pragma unroll
            for (int mm = 0; mm < 8; mm++) {
                accp[mm][0] = bA.x; accp[mm][1] = bA.y;
                accp[mm][2] = bB.x; accp[mm][3] = bB.y;
            }
            for (int kt = 0; kt < 8; kt++) {
                int nxt = cur + 1; if (nxt == 3) nxt = 0;
                bool more = (kt < 7) || (step < HOR - 1);
                if (more) {
                    int ntile = (kt + 1) & 7;
                    const float4* src = reinterpret_cast<const float4*>(w2 + ntile * KT * 256);
                    float4* dst = reinterpret_cast<float4*>(s_wt + nxt * 8192);
#pragma unroll
                    for (int i = 0; i < 8; i++) {
                        int idx = tid + i * 256;
                        cp16(reinterpret_cast<float*>(dst + idx),
                             reinterpret_cast<const float*>(src + idx));
                    }
                    cp_commit();
                    cp_wait1();
                } else {
                    cp_wait0();
                }
                __syncthreads();

                const float* W = s_wt + cur * 8192;
                const float* Hbase = s_h + mrow * 256 + kt * KT;
#pragma unroll 2
                for (int kk = 0; kk < KT; kk += 4) {
                    ulonglong2 wA2[4], wB2[4];
#pragma unroll
                    for (int t = 0; t < 4; t++) {
                        wA2[t] = *reinterpret_cast<const ulonglong2*>(W + (kk + t) * 256 + J0);
                        wB2[t] = *reinterpret_cast<const ulonglong2*>(W + (kk + t) * 256 + J1);
                    }
#pragma unroll
                    for (int mm = 0; mm < 8; mm++) {
                        F4 hv = ld4s(Hbase + mm * 256 + kk);
#pragma unroll
                        for (int t = 0; t < 4; t++) {
                            u64 hd = dup2f(hv.v[t]);
                            fma2(accp[mm][0], hd, wA2[t].x);
                            fma2(accp[mm][1], hd, wA2[t].y);
                            fma2(accp[mm][2], hd, wB2[t].x);
                            fma2(accp[mm][3], hd, wB2[t].y);
                        }
                    }
                }
                cur = nxt;
            }
        }
        {
#pragma unroll
            for (int mm = 0; mm < 8; mm++)
#pragma unroll
                for (int p = 0; p < 4; p++) accp[mm][p] = relu2(accp[mm][p]);

            for (int d = 0; d < 9; d++) {
                ulonglong2 wA2 = *reinterpret_cast<const ulonglong2*>(s_w3t + d * 256 + J0);
                ulonglong2 wB2 = *reinterpret_cast<const ulonglong2*>(s_w3t + d * 256 + J1);
                float pd[8];
#pragma unroll
                for (int mm = 0; mm < 8; mm++) {
                    u64 p = 0ULL;
                    fma2(p, accp[mm][0], wA2.x);
                    fma2(p, accp[mm][1], wA2.y);
                    fma2(p, accp[mm][2], wB2.x);
                    fma2(p, accp[mm][3], wB2.y);
                    float2 f = unpk(p);
                    pd[mm] = f.x + f.y;
                }
#pragma unroll
                for (int off = 16; off >= 1; off >>= 1) {
#pragma unroll
                    for (int mm = 0; mm < 8; mm++)
                        pd[mm] += __shfl_xor_sync(0xffffffffu, pd[mm], off);
                }
                if (ji == 0) {
#pragma unroll
                    for (int mm = 0; mm < 8; mm++) {
                        float sv = pd[mm] + s_b3[d];
                        s_inp[(mrow + mm) * 16 + d] = sv;
                        if (d < 3) {
                            float t = sv - s_tgt[(mrow + mm) * 3 + d];
                            cm[mm] = fmaf(t, t, cm[mm]);
                        }
                    }
                }
            }
            __syncwarp();
        }
    }

    if (ji == 0) {
#pragma unroll
        for (int mm = 0; mm < 8; mm++)
            g_cost[s_idx * BB + b0 + mrow + mm] = cm[mm];
    }
#endif // !HAS_TC
}

// ---------------- select ----------------------------------------------------
__global__ __launch_bounds__(256) void select_kernel(float* __restrict__ out)
{
    int b = blockIdx.x*blockDim.x + threadIdx.x;
    if (b >= BB) return;
    float best = g_cost[b]; int bi = 0;
#pragma unroll
    for (int s=1;s<SSAMP;s++){
        float c = g_cost[s*BB+b];
        if (c < best){ best = c; bi = s; }
    }
    const float* src = g_cand + (bi*BB+b)*7;
#pragma unroll
    for (int a=0;a<7;a++) out[b*7+a] = src[a];
}

// ---------------- launch -----------------------------------------------------
extern "C" void kernel_launch(void* const* d_in, const int* in_sizes, int n_in,
                              void* d_out, int out_size)
{
    (void)in_sizes; (void)n_in; (void)out_size;
    const float* state   = (const float*)d_in[0];
    const float* proprio = (const float*)d_in[1];
    const float* target  = (const float*)d_in[2];
    const float* noise   = (const float*)d_in[3];
    const float* pw1 = (const float*)d_in[4];
    const float* pb1 = (const float*)d_in[5];
    const float* pw2 = (const float*)d_in[6];
    const float* pb2 = (const float*)d_in[7];
    const float* w1  = (const float*)d_in[8];
    const float* b1  = (const float*)d_in[9];
    const float* w2  = (const float*)d_in[10];
    const float* b2  = (const float*)d_in[11];
    const float* w3  = (const float*)d_in[12];
    const float* b3  = (const float*)d_in[13];
    float* out = (float*)d_out;

    cudaFuncSetAttribute(rollout_tc, cudaFuncAttributeMaxDynamicSharedMemorySize, SMEMSZ);
    cudaFuncSetAttribute(rollout_fb, cudaFuncAttributeMaxDynamicSharedMemorySize, FB_BYTES);

    prep_w1<<<32, 256>>>(w1);
    prep_w2<<<256, 256>>>(w2);
    proposal_kernel<<<BB/8, 256>>>(state, proprio, noise, pw1, pb1, pw2, pb2);
    rollout_tc<<<(SSAMP*BB)/128, 256, SMEMSZ>>>(state, target, b1, b2, b3, w3);
    rollout_fb<<<(SSAMP*BB)/TILE_M, 256, FB_BYTES>>>(state, target, w1, b1, w2, b2, w3, b3);
    select_kernel<<<BB/256, 256>>>(out);
}